// round 1
// baseline (speedup 1.0000x reference)
#include <cuda_runtime.h>

// Problem: DilatedAttention  q,k,v: [4, 8192, 16, 64] f32 -> out same shape.
// Groups (derived from reference): (g, r, segment, offset, hmin):
//   g0: (6, 1, 2048, 0, 0)   eligible pos: all,       heads 0..5
//   g1: (5, 2, 4096, 1, 5)   eligible pos: p%2==1,    heads 5..9
//   g2: (5, 4, 8192, 2, 10)  eligible pos: p%4==2,    heads 10..14
// head 15 never written (faithful to reference's i*g indexing).
// Per eligible position: gxg attention over the HEAD axis (d=64), then
// x normalized by sum of x over all eligible positions per (b, head, d),
// scatter-added, divided by num_groups (3).

#define SEQ   8192
#define BATCH 4
#define HEADS 16
#define DIM   64

// scratch (static device globals; no allocation allowed)
#define X0_BASE 0
#define X0_SIZE (BATCH*8192*6*DIM)          // 12,582,912
#define X1_BASE (X0_BASE + X0_SIZE)
#define X1_SIZE (BATCH*4096*5*DIM)          //  5,242,880
#define X2_BASE (X1_BASE + X1_SIZE)         // 17,825,792
#define X2_SIZE (BATCH*2048*5*DIM)          //  2,621,440
#define X_TOTAL (X2_BASE + X2_SIZE)         // 20,447,232

#define S0_BASE 0
#define S0_SIZE (BATCH*6*DIM)               // 1536
#define S1_BASE (S0_BASE + S0_SIZE)
#define S1_SIZE (BATCH*5*DIM)               // 1280
#define S2_BASE (S1_BASE + S1_SIZE)         // 2816
#define S_TOTAL (S2_BASE + BATCH*5*DIM)     // 4096

__device__ float g_x[X_TOTAL];
__device__ float g_sums[S_TOTAL];
__device__ float g_rsums[S_TOTAL];

__global__ void zero_sums_kernel() {
    int i = blockIdx.x * blockDim.x + threadIdx.x;
    if (i < S_TOTAL) g_sums[i] = 0.0f;
}

__global__ void rsums_kernel() {
    int i = blockIdx.x * blockDim.x + threadIdx.x;
    if (i < S_TOTAL) g_rsums[i] = 1.0f / (3.0f * g_sums[i]);
}

// Pass 1: per eligible position, head-axis attention.
// warp = 2 positions (halves), 16 lanes x float4 over d=64.
// G heads, R dilation, OFF offset, HMIN first head, PB eligible-positions per
// batch, PPW position-pairs per warp, XBASE/SUMBASE scratch offsets.
template<int G, int R, int OFF, int HMIN, int PB, int PPW, int XBASE, int SUMBASE>
__global__ void __launch_bounds__(256) pass1_kernel(
    const float* __restrict__ q,
    const float* __restrict__ k,
    const float* __restrict__ v)
{
    const int tid  = threadIdx.x;
    const int w    = tid >> 5;     // warp in block (0..7)
    const int lane = tid & 31;
    const int half = lane >> 4;    // 0: even position of pair, 1: odd
    const int lh   = lane & 15;    // lane within half; owns dims [4*lh, 4*lh+4)

    constexpr int POS_PER_BLOCK = 16 * PPW; // 8 warps * 2 * PPW
    __shared__ float sblk[G * 64];
    for (int i = tid; i < G * 64; i += 256) sblk[i] = 0.0f;
    __syncthreads();

    const int blockBase = blockIdx.x * POS_PER_BLOCK; // eligible-position index (global)
    const int b = blockBase / PB;                     // POS_PER_BLOCK divides PB

    float4 acc[G];
    #pragma unroll
    for (int a = 0; a < G; a++) acc[a] = make_float4(0.f, 0.f, 0.f, 0.f);

    #pragma unroll 1
    for (int it = 0; it < PPW; it++) {
        const int j  = blockBase + w * (2 * PPW) + 2 * it + half; // global eligible idx
        const int jb = j - b * PB;                                // within batch
        const int p  = jb * R + OFF;                              // sequence position
        const int rowbase = (((b * SEQ + p) * HEADS + HMIN) * DIM) + 4 * lh;

        float4 qv[G], kv[G];
        #pragma unroll
        for (int a = 0; a < G; a++) {
            qv[a] = *reinterpret_cast<const float4*>(q + rowbase + a * DIM);
            kv[a] = *reinterpret_cast<const float4*>(k + rowbase + a * DIM);
        }

        // partial scores over this lane's 4 dims
        float s[G][G];
        #pragma unroll
        for (int a = 0; a < G; a++)
            #pragma unroll
            for (int c = 0; c < G; c++)
                s[a][c] = qv[a].x * kv[c].x + qv[a].y * kv[c].y
                        + qv[a].z * kv[c].z + qv[a].w * kv[c].w;

        // butterfly reduce within each 16-lane half (masks <16 keep halves apart)
        #pragma unroll
        for (int m = 1; m < 16; m <<= 1)
            #pragma unroll
            for (int a = 0; a < G; a++)
                #pragma unroll
                for (int c = 0; c < G; c++)
                    s[a][c] += __shfl_xor_sync(0xffffffffu, s[a][c], m);

        // scale = 1/sqrt(64)
        #pragma unroll
        for (int a = 0; a < G; a++)
            #pragma unroll
            for (int c = 0; c < G; c++)
                s[a][c] *= 0.125f;

        float4 vv[G];
        #pragma unroll
        for (int a = 0; a < G; a++)
            vv[a] = *reinterpret_cast<const float4*>(v + rowbase + a * DIM);

        const int xbase = XBASE + (j * G) * DIM + 4 * lh;
        #pragma unroll
        for (int a = 0; a < G; a++) {
            float mx = s[a][0];
            #pragma unroll
            for (int c = 1; c < G; c++) mx = fmaxf(mx, s[a][c]);
            float e[G];
            float tot = 0.0f;
            #pragma unroll
            for (int c = 0; c < G; c++) { e[c] = __expf(s[a][c] - mx); tot += e[c]; }
            const float rinv = 1.0f / tot;
            float4 xo = make_float4(0.f, 0.f, 0.f, 0.f);
            #pragma unroll
            for (int c = 0; c < G; c++) {
                const float wt = e[c] * rinv;
                xo.x += wt * vv[c].x; xo.y += wt * vv[c].y;
                xo.z += wt * vv[c].z; xo.w += wt * vv[c].w;
            }
            *reinterpret_cast<float4*>(g_x + xbase + a * DIM) = xo;
            acc[a].x += xo.x; acc[a].y += xo.y; acc[a].z += xo.z; acc[a].w += xo.w;
        }
    }

    // combine the two halves (same (head, dim) slots)
    #pragma unroll
    for (int a = 0; a < G; a++) {
        acc[a].x += __shfl_down_sync(0xffffffffu, acc[a].x, 16);
        acc[a].y += __shfl_down_sync(0xffffffffu, acc[a].y, 16);
        acc[a].z += __shfl_down_sync(0xffffffffu, acc[a].z, 16);
        acc[a].w += __shfl_down_sync(0xffffffffu, acc[a].w, 16);
    }
    if (half == 0) {
        #pragma unroll
        for (int a = 0; a < G; a++) {
            atomicAdd(&sblk[a * 64 + 4 * lh + 0], acc[a].x);
            atomicAdd(&sblk[a * 64 + 4 * lh + 1], acc[a].y);
            atomicAdd(&sblk[a * 64 + 4 * lh + 2], acc[a].z);
            atomicAdd(&sblk[a * 64 + 4 * lh + 3], acc[a].w);
        }
    }
    __syncthreads();
    for (int i = tid; i < G * 64; i += 256)
        atomicAdd(&g_sums[SUMBASE + b * (G * 64) + i], sblk[i]);
}

// Pass 2: write every output element (zeros where no group contributes).
// One thread per float4. idx layout: d4 (16) | h (16) | p (8192) | b (4).
__global__ void __launch_bounds__(256) pass2_kernel(float* __restrict__ out)
{
    const int idx = blockIdx.x * 256 + threadIdx.x; // 8,388,608 float4s
    const int d4 = idx & 15;
    const int h  = (idx >> 4) & 15;
    const int p  = (idx >> 8) & 8191;
    const int b  = idx >> 21;

    float4 val = make_float4(0.f, 0.f, 0.f, 0.f);

    if (h < 6) { // group 0: all positions, heads 0..5
        const int j = b * 8192 + p;
        const float4 xv = *reinterpret_cast<const float4*>(g_x + X0_BASE + ((j * 6 + h) << 6) + (d4 << 2));
        const float4 rv = *reinterpret_cast<const float4*>(g_rsums + S0_BASE + (((b * 6 + h) << 6) + (d4 << 2)));
        val.x += xv.x * rv.x; val.y += xv.y * rv.y;
        val.z += xv.z * rv.z; val.w += xv.w * rv.w;
    }
    if (h >= 5 && h < 10 && (p & 1) == 1) { // group 1: odd positions, heads 5..9
        const int j  = b * 4096 + (p >> 1);
        const int hh = h - 5;
        const float4 xv = *reinterpret_cast<const float4*>(g_x + X1_BASE + ((j * 5 + hh) << 6) + (d4 << 2));
        const float4 rv = *reinterpret_cast<const float4*>(g_rsums + S1_BASE + (((b * 5 + hh) << 6) + (d4 << 2)));
        val.x += xv.x * rv.x; val.y += xv.y * rv.y;
        val.z += xv.z * rv.z; val.w += xv.w * rv.w;
    }
    if (h >= 10 && h < 15 && (p & 3) == 2) { // group 2: pos%4==2, heads 10..14
        const int j  = b * 2048 + (p >> 2);
        const int hh = h - 10;
        const float4 xv = *reinterpret_cast<const float4*>(g_x + X2_BASE + ((j * 5 + hh) << 6) + (d4 << 2));
        const float4 rv = *reinterpret_cast<const float4*>(g_rsums + S2_BASE + (((b * 5 + hh) << 6) + (d4 << 2)));
        val.x += xv.x * rv.x; val.y += xv.y * rv.y;
        val.z += xv.z * rv.z; val.w += xv.w * rv.w;
    }

    reinterpret_cast<float4*>(out)[idx] = val;
}

extern "C" void kernel_launch(void* const* d_in, const int* in_sizes, int n_in,
                              void* d_out, int out_size)
{
    const float* q = (const float*)d_in[0];
    const float* k = (const float*)d_in[1];
    const float* v = (const float*)d_in[2];
    float* out = (float*)d_out;

    zero_sums_kernel<<<16, 256>>>();

    // g0: G=6, r=1, off=0, hmin=0,  PB=8192, PPW=4 -> 64 pos/block, 512 blocks
    pass1_kernel<6, 1, 0, 0, 8192, 4, X0_BASE, S0_BASE><<<512, 256>>>(q, k, v);
    // g1: G=5, r=2, off=1, hmin=5,  PB=4096, PPW=2 -> 32 pos/block, 512 blocks
    pass1_kernel<5, 2, 1, 5, 4096, 2, X1_BASE, S1_BASE><<<512, 256>>>(q, k, v);
    // g2: G=5, r=4, off=2, hmin=10, PB=2048, PPW=1 -> 16 pos/block, 512 blocks
    pass1_kernel<5, 4, 2, 10, 2048, 1, X2_BASE, S2_BASE><<<512, 256>>>(q, k, v);

    rsums_kernel<<<16, 256>>>();

    // 8,388,608 float4 outputs / 256 = 32768 blocks
    pass2_kernel<<<32768, 256>>>(out);
}

// round 2
// speedup vs baseline: 1.0880x; 1.0880x over previous
#include <cuda_runtime.h>

// Problem: DilatedAttention  q,k,v: [4, 8192, 16, 64] f32 -> out same shape.
// Groups (derived from reference): (g, r, segment, offset, hmin):
//   g0: (6, 1, 2048, 0, 0)   eligible pos: all,       heads 0..5
//   g1: (5, 2, 4096, 1, 5)   eligible pos: p%2==1,    heads 5..9
//   g2: (5, 4, 8192, 2, 10)  eligible pos: p%4==2,    heads 10..14
// head 15 never written (faithful to reference's i*g indexing).
// Per eligible position: gxg attention over the HEAD axis (d=64), then
// x normalized by sum of x over all eligible positions per (b, head, d),
// scatter-added, divided by num_groups (3).

#define SEQ   8192
#define BATCH 4
#define HEADS 16
#define DIM   64

// scratch (static device globals; no allocation allowed)
#define X0_BASE 0
#define X0_SIZE (BATCH*8192*6*DIM)          // 12,582,912
#define X1_BASE (X0_BASE + X0_SIZE)
#define X1_SIZE (BATCH*4096*5*DIM)          //  5,242,880
#define X2_BASE (X1_BASE + X1_SIZE)         // 17,825,792
#define X2_SIZE (BATCH*2048*5*DIM)          //  2,621,440
#define X_TOTAL (X2_BASE + X2_SIZE)         // 20,447,232

#define S0_BASE 0
#define S0_SIZE (BATCH*6*DIM)               // 1536
#define S1_BASE (S0_BASE + S0_SIZE)
#define S1_SIZE (BATCH*5*DIM)               // 1280
#define S2_BASE (S1_BASE + S1_SIZE)         // 2816
#define S_TOTAL (S2_BASE + BATCH*5*DIM)     // 4096

__device__ float g_x[X_TOTAL];
__device__ float g_sums[S_TOTAL];
__device__ float g_rsums[S_TOTAL];

__global__ void zero_sums_kernel() {
    int i = blockIdx.x * blockDim.x + threadIdx.x;
    if (i < S_TOTAL) g_sums[i] = 0.0f;
}

__global__ void rsums_kernel() {
    int i = blockIdx.x * blockDim.x + threadIdx.x;
    if (i < S_TOTAL) g_rsums[i] = 1.0f / (3.0f * g_sums[i]);
}

// Pass-1 body: one block = 16 eligible positions (8 warps x 2 halves).
// Lane layout: 16 lanes per position, lane lh owns dims [4*lh, 4*lh+4).
// K and V are streamed one head at a time to keep the live register set
// around 70 (qv 24 + scores 36 + one streamed float4) -- no spills.
template<int G, int R, int OFF, int HMIN, int PB, int XBASE, int SUMBASE>
__device__ __forceinline__ void pass1_body(
    int blockOffset, float* sblk,
    const float* __restrict__ q,
    const float* __restrict__ k,
    const float* __restrict__ v)
{
    const int tid  = threadIdx.x;
    const int w    = tid >> 5;     // warp in block (0..7)
    const int lane = tid & 31;
    const int half = lane >> 4;    // which position of the warp's pair
    const int lh   = lane & 15;    // lane within half; owns dims [4*lh, 4*lh+4)

    for (int i = tid; i < G * 64; i += 256) sblk[i] = 0.0f;
    __syncthreads();

    const int blockBase = blockOffset * 16;           // eligible-position index (global)
    const int b  = blockBase / PB;                    // 16 divides PB
    const int j  = blockBase + w * 2 + half;          // global eligible idx
    const int jb = j - b * PB;                        // within batch
    const int p  = jb * R + OFF;                      // sequence position
    const int rowbase = (((b * SEQ + p) * HEADS + HMIN) * DIM) + 4 * lh;

    // Load all Q heads (G float4 = up to 24 regs), stream K per head.
    float4 qv[G];
    #pragma unroll
    for (int a = 0; a < G; a++)
        qv[a] = *reinterpret_cast<const float4*>(q + rowbase + a * DIM);

    float s[G][G];
    #pragma unroll
    for (int c = 0; c < G; c++) {
        const float4 kc = *reinterpret_cast<const float4*>(k + rowbase + c * DIM);
        #pragma unroll
        for (int a = 0; a < G; a++)
            s[a][c] = qv[a].x * kc.x + qv[a].y * kc.y
                    + qv[a].z * kc.z + qv[a].w * kc.w;
    }

    // Butterfly reduce within each 16-lane half (masks <16 keep halves apart).
    #pragma unroll
    for (int m = 1; m < 16; m <<= 1)
        #pragma unroll
        for (int a = 0; a < G; a++)
            #pragma unroll
            for (int c = 0; c < G; c++)
                s[a][c] += __shfl_xor_sync(0xffffffffu, s[a][c], m);

    // Softmax per row (scale = 1/sqrt(64) = 0.125), weights left in s.
    #pragma unroll
    for (int a = 0; a < G; a++) {
        float mx = s[a][0];
        #pragma unroll
        for (int c = 1; c < G; c++) mx = fmaxf(mx, s[a][c]);
        float tot = 0.0f;
        #pragma unroll
        for (int c = 0; c < G; c++) {
            s[a][c] = __expf(s[a][c] * 0.125f - mx * 0.125f);
            tot += s[a][c];
        }
        const float rinv = 1.0f / tot;
        #pragma unroll
        for (int c = 0; c < G; c++) s[a][c] *= rinv;
    }

    // AV: stream V per head, accumulate all G outputs.
    float4 xo[G];
    #pragma unroll
    for (int a = 0; a < G; a++) xo[a] = make_float4(0.f, 0.f, 0.f, 0.f);
    #pragma unroll
    for (int c = 0; c < G; c++) {
        const float4 vc = *reinterpret_cast<const float4*>(v + rowbase + c * DIM);
        #pragma unroll
        for (int a = 0; a < G; a++) {
            xo[a].x += s[a][c] * vc.x; xo[a].y += s[a][c] * vc.y;
            xo[a].z += s[a][c] * vc.z; xo[a].w += s[a][c] * vc.w;
        }
    }

    const int xbase = XBASE + (j * G) * DIM + 4 * lh;
    #pragma unroll
    for (int a = 0; a < G; a++)
        *reinterpret_cast<float4*>(g_x + xbase + a * DIM) = xo[a];

    // Combine the two halves (same (head, dim) slots), then block-accumulate.
    #pragma unroll
    for (int a = 0; a < G; a++) {
        xo[a].x += __shfl_down_sync(0xffffffffu, xo[a].x, 16);
        xo[a].y += __shfl_down_sync(0xffffffffu, xo[a].y, 16);
        xo[a].z += __shfl_down_sync(0xffffffffu, xo[a].z, 16);
        xo[a].w += __shfl_down_sync(0xffffffffu, xo[a].w, 16);
    }
    if (half == 0) {
        #pragma unroll
        for (int a = 0; a < G; a++) {
            atomicAdd(&sblk[a * 64 + 4 * lh + 0], xo[a].x);
            atomicAdd(&sblk[a * 64 + 4 * lh + 1], xo[a].y);
            atomicAdd(&sblk[a * 64 + 4 * lh + 2], xo[a].z);
            atomicAdd(&sblk[a * 64 + 4 * lh + 3], xo[a].w);
        }
    }
    __syncthreads();
    for (int i = tid; i < G * 64; i += 256)
        atomicAdd(&g_sums[SUMBASE + b * (G * 64) + i], sblk[i]);
}

// Fused pass 1: all three groups in one full-chip launch.
// Blocks [0,2048): g0, [2048,3072): g1, [3072,3584): g2.
__global__ void __launch_bounds__(256) pass1_fused_kernel(
    const float* __restrict__ q,
    const float* __restrict__ k,
    const float* __restrict__ v)
{
    __shared__ float sblk[6 * 64];
    const int bx = blockIdx.x;
    if (bx < 2048) {
        pass1_body<6, 1, 0, 0, 8192, X0_BASE, S0_BASE>(bx, sblk, q, k, v);
    } else if (bx < 3072) {
        pass1_body<5, 2, 1, 5, 4096, X1_BASE, S1_BASE>(bx - 2048, sblk, q, k, v);
    } else {
        pass1_body<5, 4, 2, 10, 2048, X2_BASE, S2_BASE>(bx - 3072, sblk, q, k, v);
    }
}

// Pass 2: write every output element (zeros where no group contributes).
// One thread per float4. idx layout: d4 (16) | h (16) | p (8192) | b (4).
__global__ void __launch_bounds__(256) pass2_kernel(float* __restrict__ out)
{
    const int idx = blockIdx.x * 256 + threadIdx.x; // 8,388,608 float4s
    const int d4 = idx & 15;
    const int h  = (idx >> 4) & 15;
    const int p  = (idx >> 8) & 8191;
    const int b  = idx >> 21;

    float4 val = make_float4(0.f, 0.f, 0.f, 0.f);

    if (h < 6) { // group 0: all positions, heads 0..5
        const int j = b * 8192 + p;
        const float4 xv = *reinterpret_cast<const float4*>(g_x + X0_BASE + ((j * 6 + h) << 6) + (d4 << 2));
        const float4 rv = *reinterpret_cast<const float4*>(g_rsums + S0_BASE + (((b * 6 + h) << 6) + (d4 << 2)));
        val.x += xv.x * rv.x; val.y += xv.y * rv.y;
        val.z += xv.z * rv.z; val.w += xv.w * rv.w;
    }
    if (h >= 5 && h < 10 && (p & 1) == 1) { // group 1: odd positions, heads 5..9
        const int j  = b * 4096 + (p >> 1);
        const int hh = h - 5;
        const float4 xv = *reinterpret_cast<const float4*>(g_x + X1_BASE + ((j * 5 + hh) << 6) + (d4 << 2));
        const float4 rv = *reinterpret_cast<const float4*>(g_rsums + S1_BASE + (((b * 5 + hh) << 6) + (d4 << 2)));
        val.x += xv.x * rv.x; val.y += xv.y * rv.y;
        val.z += xv.z * rv.z; val.w += xv.w * rv.w;
    }
    if (h >= 10 && h < 15 && (p & 3) == 2) { // group 2: pos%4==2, heads 10..14
        const int j  = b * 2048 + (p >> 2);
        const int hh = h - 10;
        const float4 xv = *reinterpret_cast<const float4*>(g_x + X2_BASE + ((j * 5 + hh) << 6) + (d4 << 2));
        const float4 rv = *reinterpret_cast<const float4*>(g_rsums + S2_BASE + (((b * 5 + hh) << 6) + (d4 << 2)));
        val.x += xv.x * rv.x; val.y += xv.y * rv.y;
        val.z += xv.z * rv.z; val.w += xv.w * rv.w;
    }

    reinterpret_cast<float4*>(out)[idx] = val;
}

extern "C" void kernel_launch(void* const* d_in, const int* in_sizes, int n_in,
                              void* d_out, int out_size)
{
    const float* q = (const float*)d_in[0];
    const float* k = (const float*)d_in[1];
    const float* v = (const float*)d_in[2];
    float* out = (float*)d_out;

    zero_sums_kernel<<<16, 256>>>();

    // Fused pass 1: 2048 (g0) + 1024 (g1) + 512 (g2) blocks, 16 positions each.
    pass1_fused_kernel<<<3584, 256>>>(q, k, v);

    rsums_kernel<<<16, 256>>>();

    // 8,388,608 float4 outputs / 256 = 32768 blocks
    pass2_kernel<<<32768, 256>>>(out);
}